// round 12
// baseline (speedup 1.0000x reference)
#include <cuda_runtime.h>
#include <cuda_bf16.h>

// MoE gather-combine: out[t, :] = sum_k scores[t*K+k] * flat[slots[t*K+k], :]
// Best-measured shape (R5): 1 CTA/token, 256 threads, 2 float4/thread/row
// -> 4 independent LDG.128 in flight at ~80% occ. This round's single
// change: output stores use st.global.wt (write-through) instead of .cs,
// to keep the never-re-read 64MB write stream from displacing gather-read
// lines in L2. All other experiments (depth/width/persistence/prefetch)
// measured slower; this is the last untested r/w-interaction knob.

__device__ __forceinline__ unsigned long long mk_evict_last_policy() {
    unsigned long long pol;
    asm("createpolicy.fractional.L2::evict_last.b64 %0, 1.0;" : "=l"(pol));
    return pol;
}

__device__ __forceinline__ float4 ldg_el_f4(const float4* p, unsigned long long pol) {
    float4 v;
    asm volatile("ld.global.nc.L2::cache_hint.v4.f32 {%0,%1,%2,%3}, [%4], %5;"
                 : "=f"(v.x), "=f"(v.y), "=f"(v.z), "=f"(v.w)
                 : "l"(p), "l"(pol));
    return v;
}

__device__ __forceinline__ void stwt_f4(float4* p, float4 v) {
    asm volatile("st.global.wt.v4.f32 [%0], {%1,%2,%3,%4};"
                 :: "l"(p), "f"(v.x), "f"(v.y), "f"(v.z), "f"(v.w) : "memory");
}

__global__ void __launch_bounds__(256, 8)
moe_gather_h2048_kernel(const float* __restrict__ flat,
                        const float* __restrict__ scores,
                        const int* __restrict__ slots,
                        const int* __restrict__ topk_p,
                        float* __restrict__ out,
                        int n_tokens) {
    const int token = blockIdx.x;
    if (token >= n_tokens) return;
    const int K = topk_p[0];
    const unsigned long long pol = mk_evict_last_policy();

    const int t0 = threadIdx.x;          // float4 lane 0..255
    const int t1 = threadIdx.x + 256;    // float4 lane 256..511
    float4* orow = reinterpret_cast<float4*>(out + (size_t)token * 2048);

    if (K == 2) {
        const int   s0 = __ldg(&slots[token * 2 + 0]);
        const int   s1 = __ldg(&slots[token * 2 + 1]);
        const float w0 = __ldg(&scores[token * 2 + 0]);
        const float w1 = __ldg(&scores[token * 2 + 1]);

        const float4* r0 = reinterpret_cast<const float4*>(flat + (size_t)s0 * 2048);
        const float4* r1 = reinterpret_cast<const float4*>(flat + (size_t)s1 * 2048);

        // 4 independent LDG.128, all in flight before any FMA.
        float4 a0 = ldg_el_f4(&r0[t0], pol);
        float4 a1 = ldg_el_f4(&r0[t1], pol);
        float4 b0 = ldg_el_f4(&r1[t0], pol);
        float4 b1 = ldg_el_f4(&r1[t1], pol);

        float4 acc0, acc1;
        acc0.x = fmaf(w1, b0.x, w0 * a0.x);
        acc0.y = fmaf(w1, b0.y, w0 * a0.y);
        acc0.z = fmaf(w1, b0.z, w0 * a0.z);
        acc0.w = fmaf(w1, b0.w, w0 * a0.w);
        acc1.x = fmaf(w1, b1.x, w0 * a1.x);
        acc1.y = fmaf(w1, b1.y, w0 * a1.y);
        acc1.z = fmaf(w1, b1.z, w0 * a1.z);
        acc1.w = fmaf(w1, b1.w, w0 * a1.w);

        stwt_f4(&orow[t0], acc0);
        stwt_f4(&orow[t1], acc1);
        return;
    }

    // Generic K path.
    float4 acc0 = make_float4(0.f, 0.f, 0.f, 0.f);
    float4 acc1 = make_float4(0.f, 0.f, 0.f, 0.f);
    for (int k = 0; k < K; ++k) {
        const int   slot = __ldg(&slots[token * K + k]);
        const float w    = __ldg(&scores[token * K + k]);
        const float4* row = reinterpret_cast<const float4*>(flat + (size_t)slot * 2048);
        float4 v0 = ldg_el_f4(&row[t0], pol);
        float4 v1 = ldg_el_f4(&row[t1], pol);
        acc0.x = fmaf(w, v0.x, acc0.x);
        acc0.y = fmaf(w, v0.y, acc0.y);
        acc0.z = fmaf(w, v0.z, acc0.z);
        acc0.w = fmaf(w, v0.w, acc0.w);
        acc1.x = fmaf(w, v1.x, acc1.x);
        acc1.y = fmaf(w, v1.y, acc1.y);
        acc1.z = fmaf(w, v1.z, acc1.z);
        acc1.w = fmaf(w, v1.w, acc1.w);
    }
    stwt_f4(&orow[t0], acc0);
    stwt_f4(&orow[t1], acc1);
}

// Generic fallback for any hidden (scalar loop within row).
__global__ void moe_gather_generic_kernel(const float* __restrict__ flat,
                                          const float* __restrict__ scores,
                                          const int* __restrict__ slots,
                                          const int* __restrict__ topk_p,
                                          float* __restrict__ out,
                                          int n_tokens, int hidden) {
    const int token = blockIdx.x;
    if (token >= n_tokens) return;
    const int K = topk_p[0];

    for (int h = threadIdx.x; h < hidden; h += blockDim.x) {
        float acc = 0.f;
        for (int k = 0; k < K; ++k) {
            const int   slot = slots[token * K + k];
            const float w    = scores[token * K + k];
            acc = fmaf(w, flat[(size_t)slot * hidden + h], acc);
        }
        out[(size_t)token * hidden + h] = acc;
    }
}

extern "C" void kernel_launch(void* const* d_in, const int* in_sizes, int n_in,
                              void* d_out, int out_size) {
    const float* flat   = (const float*)d_in[0];   // moe_output, [n_slots, hidden]
    const float* scores = (const float*)d_in[1];   // [n_slots]
    const int*   slots  = (const int*)d_in[2];     // [n_slots]
    const int*   topk_p = (const int*)d_in[3];     // scalar top_k (device)

    const int n_slots = in_sizes[1];
    const int hidden  = in_sizes[0] / n_slots;
    const int n_tokens = out_size / hidden;

    float* out = (float*)d_out;

    if (hidden == 2048) {
        moe_gather_h2048_kernel<<<n_tokens, 256>>>(flat, scores, slots, topk_p,
                                                   out, n_tokens);
    } else {
        moe_gather_generic_kernel<<<n_tokens, 256>>>(flat, scores, slots, topk_p,
                                                     out, n_tokens, hidden);
    }
}

// round 13
// speedup vs baseline: 1.0748x; 1.0748x over previous
#include <cuda_runtime.h>
#include <cuda_bf16.h>

// MoE gather-combine: out[t, :] = sum_k scores[t*K+k] * flat[slots[t*K+k], :]
// FINAL (best of 12 measured rounds = R5 config): 1 CTA per token, 256
// threads, 2 float4/thread/row -> K=2 gives 4 independent LDG.128 in
// flight per thread at ~80% occupancy. Empirically the optimum of the
// MLP-vs-occupancy trade for this mixed random-8KB-gather-read +
// streaming-write pattern:
//   deeper ILP (8 loads/thr, 128t): 26.9us  | narrower (2 loads/thr): 27.6us
//   persistent (+idx prefetch): 24.4us      | L2 row prefetch: 30.7us
//   v8 256-bit loads: 24.4us                | .wt stores: +7MB DRAM, no gain
// Store policy sweep: default 24.6 > .cs 23.8 < .wt 24.1  -> .cs.
// ~4.9TB/s effective HBM, ~117MB compulsory traffic/replay; L2 carveout is
// 0 and cudaDeviceSetLimit is banned, so L2 retention is not controllable.

__device__ __forceinline__ unsigned long long mk_evict_last_policy() {
    unsigned long long pol;
    asm("createpolicy.fractional.L2::evict_last.b64 %0, 1.0;" : "=l"(pol));
    return pol;
}

__device__ __forceinline__ float4 ldg_el_f4(const float4* p, unsigned long long pol) {
    float4 v;
    asm volatile("ld.global.nc.L2::cache_hint.v4.f32 {%0,%1,%2,%3}, [%4], %5;"
                 : "=f"(v.x), "=f"(v.y), "=f"(v.z), "=f"(v.w)
                 : "l"(p), "l"(pol));
    return v;
}

__device__ __forceinline__ void stcs_f4(float4* p, float4 v) {
    asm volatile("st.global.cs.v4.f32 [%0], {%1,%2,%3,%4};"
                 :: "l"(p), "f"(v.x), "f"(v.y), "f"(v.z), "f"(v.w) : "memory");
}

__global__ void __launch_bounds__(256, 8)
moe_gather_h2048_kernel(const float* __restrict__ flat,
                        const float* __restrict__ scores,
                        const int* __restrict__ slots,
                        const int* __restrict__ topk_p,
                        float* __restrict__ out,
                        int n_tokens) {
    const int token = blockIdx.x;
    if (token >= n_tokens) return;
    const int K = topk_p[0];
    const unsigned long long pol = mk_evict_last_policy();

    const int t0 = threadIdx.x;          // float4 lane 0..255
    const int t1 = threadIdx.x + 256;    // float4 lane 256..511
    float4* orow = reinterpret_cast<float4*>(out + (size_t)token * 2048);

    if (K == 2) {
        const int   s0 = __ldg(&slots[token * 2 + 0]);
        const int   s1 = __ldg(&slots[token * 2 + 1]);
        const float w0 = __ldg(&scores[token * 2 + 0]);
        const float w1 = __ldg(&scores[token * 2 + 1]);

        const float4* r0 = reinterpret_cast<const float4*>(flat + (size_t)s0 * 2048);
        const float4* r1 = reinterpret_cast<const float4*>(flat + (size_t)s1 * 2048);

        // 4 independent LDG.128, all in flight before any FMA.
        float4 a0 = ldg_el_f4(&r0[t0], pol);
        float4 a1 = ldg_el_f4(&r0[t1], pol);
        float4 b0 = ldg_el_f4(&r1[t0], pol);
        float4 b1 = ldg_el_f4(&r1[t1], pol);

        float4 acc0, acc1;
        acc0.x = fmaf(w1, b0.x, w0 * a0.x);
        acc0.y = fmaf(w1, b0.y, w0 * a0.y);
        acc0.z = fmaf(w1, b0.z, w0 * a0.z);
        acc0.w = fmaf(w1, b0.w, w0 * a0.w);
        acc1.x = fmaf(w1, b1.x, w0 * a1.x);
        acc1.y = fmaf(w1, b1.y, w0 * a1.y);
        acc1.z = fmaf(w1, b1.z, w0 * a1.z);
        acc1.w = fmaf(w1, b1.w, w0 * a1.w);

        stcs_f4(&orow[t0], acc0);
        stcs_f4(&orow[t1], acc1);
        return;
    }

    // Generic K path.
    float4 acc0 = make_float4(0.f, 0.f, 0.f, 0.f);
    float4 acc1 = make_float4(0.f, 0.f, 0.f, 0.f);
    for (int k = 0; k < K; ++k) {
        const int   slot = __ldg(&slots[token * K + k]);
        const float w    = __ldg(&scores[token * K + k]);
        const float4* row = reinterpret_cast<const float4*>(flat + (size_t)slot * 2048);
        float4 v0 = ldg_el_f4(&row[t0], pol);
        float4 v1 = ldg_el_f4(&row[t1], pol);
        acc0.x = fmaf(w, v0.x, acc0.x);
        acc0.y = fmaf(w, v0.y, acc0.y);
        acc0.z = fmaf(w, v0.z, acc0.z);
        acc0.w = fmaf(w, v0.w, acc0.w);
        acc1.x = fmaf(w, v1.x, acc1.x);
        acc1.y = fmaf(w, v1.y, acc1.y);
        acc1.z = fmaf(w, v1.z, acc1.z);
        acc1.w = fmaf(w, v1.w, acc1.w);
    }
    stcs_f4(&orow[t0], acc0);
    stcs_f4(&orow[t1], acc1);
}

// Generic fallback for any hidden (scalar loop within row).
__global__ void moe_gather_generic_kernel(const float* __restrict__ flat,
                                          const float* __restrict__ scores,
                                          const int* __restrict__ slots,
                                          const int* __restrict__ topk_p,
                                          float* __restrict__ out,
                                          int n_tokens, int hidden) {
    const int token = blockIdx.x;
    if (token >= n_tokens) return;
    const int K = topk_p[0];

    for (int h = threadIdx.x; h < hidden; h += blockDim.x) {
        float acc = 0.f;
        for (int k = 0; k < K; ++k) {
            const int   slot = slots[token * K + k];
            const float w    = scores[token * K + k];
            acc = fmaf(w, flat[(size_t)slot * hidden + h], acc);
        }
        out[(size_t)token * hidden + h] = acc;
    }
}

extern "C" void kernel_launch(void* const* d_in, const int* in_sizes, int n_in,
                              void* d_out, int out_size) {
    const float* flat   = (const float*)d_in[0];   // moe_output, [n_slots, hidden]
    const float* scores = (const float*)d_in[1];   // [n_slots]
    const int*   slots  = (const int*)d_in[2];     // [n_slots]
    const int*   topk_p = (const int*)d_in[3];     // scalar top_k (device)

    const int n_slots = in_sizes[1];
    const int hidden  = in_sizes[0] / n_slots;
    const int n_tokens = out_size / hidden;

    float* out = (float*)d_out;

    if (hidden == 2048) {
        moe_gather_h2048_kernel<<<n_tokens, 256>>>(flat, scores, slots, topk_p,
                                                   out, n_tokens);
    } else {
        moe_gather_generic_kernel<<<n_tokens, 256>>>(flat, scores, slots, topk_p,
                                                     out, n_tokens, hidden);
    }
}